// round 14
// baseline (speedup 1.0000x reference)
#include <cuda_runtime.h>

#define A_ANG 192
#define DDET  576
#define W_IMG 384
#define WW    (W_IMG * W_IMG)
#define PADW  672
#define POFF  24
#define CMAGIC 12582912.0f            /* 2^23 + 2^22 */
#define CBITS  0x4B400000             /* __float_as_int(CMAGIC) */

// Scratch (__device__ globals: allocation-free). g_pad is zero-initialized at
// module load; padding slots are never written, so they stay zero across all
// graph replays (out-of-range detector taps contribute exactly 0).
__device__ float2 g_pad[A_ANG * PADW];     // 1.0 MB packed (sino, pred) table
__device__ float  g_img[WW];               // backprojection of raw sino
__device__ float  g_G[625];                // G[d][e] = sum_c w2[c,d]*w1[c,e]
__device__ float  g_B[25];                 // B[d]    = sum_c w2[c,d]*b1[c]
__device__ float  g_W[81];                 // interior 9x9 composite kernel
__device__ float  g_bias[1];               // b2 + sum_d B[d]

// ---------------------------------------------------------------------------
// Kernel 0: build composite-conv tables (1 block, trivial cost)
// ---------------------------------------------------------------------------
__global__ void __launch_bounds__(640) precompute_kernel(
    const float* __restrict__ w1, const float* __restrict__ b1,
    const float* __restrict__ w2, const float* __restrict__ b2)
{
    __shared__ float sG[625];
    const int tid = threadIdx.x;
    if (tid < 625) {
        int d = tid / 25, e = tid % 25;
        float g = 0.0f;
        #pragma unroll
        for (int c = 0; c < 16; c++) g = fmaf(w2[c * 25 + d], w1[c * 25 + e], g);
        sG[tid] = g;
        g_G[tid] = g;
    }
    if (tid < 25) {
        float s = 0.0f;
        #pragma unroll
        for (int c = 0; c < 16; c++) s = fmaf(w2[c * 25 + tid], b1[c], s);
        g_B[tid] = s;
    }
    __syncthreads();
    if (tid < 81) {
        int tty = tid / 9, ttx = tid % 9;
        float w = 0.0f;
        for (int dy = 0; dy < 5; dy++) {
            int ey = tty - dy; if (ey < 0 || ey > 4) continue;
            for (int dx = 0; dx < 5; dx++) {
                int ex = ttx - dx; if (ex < 0 || ex > 4) continue;
                w += sG[(dy * 5 + dx) * 25 + ey * 5 + ex];
            }
        }
        g_W[tid] = w;
    }
    if (tid == 0) {
        float bias = b2[0];
        #pragma unroll
        for (int c = 0; c < 16; c++) {
            float s2 = 0.0f;
            #pragma unroll
            for (int d = 0; d < 25; d++) s2 += w2[c * 25 + d];
            bias = fmaf(s2, b1[c], bias);
        }
        g_bias[0] = bias;
    }
}

// ---------------------------------------------------------------------------
// Kernel 1: composite conv (sino -> sino_pred), writes packed padded sinogram.
// Interior pixels: 9x9 kernel W (81 FMA). Border pixels: exact per-d formula.
// ---------------------------------------------------------------------------
#define CTX 32
#define CTY 8
__global__ void __launch_bounds__(CTX * CTY) conv12_kernel(
    const float* __restrict__ sino,
    const float* __restrict__ b2,
    float* __restrict__ sino_pred)
{
    __shared__ float t[CTY + 8][CTX + 8];   // 16 x 40, halo 4, zero-padded
    __shared__ float sW[81];
    __shared__ float sG[625];
    __shared__ float sB[25];
    __shared__ float sbias;

    const int tid = threadIdx.y * CTX + threadIdx.x;
    if (tid < 81) sW[tid] = g_W[tid];
    for (int i = tid; i < 625; i += CTX * CTY) sG[i] = g_G[i];
    if (tid < 25) sB[tid] = g_B[tid];
    if (tid == 255) sbias = g_bias[0];

    const int bx0 = blockIdx.x * CTX, by0 = blockIdx.y * CTY;
    for (int i = tid; i < (CTY + 8) * (CTX + 8); i += CTX * CTY) {
        int ly = i / (CTX + 8), lx = i % (CTX + 8);
        int gy = by0 - 4 + ly, gx = bx0 - 4 + lx;
        float v = 0.0f;
        if ((unsigned)gy < A_ANG && (unsigned)gx < DDET) v = sino[gy * DDET + gx];
        t[ly][lx] = v;
    }
    __syncthreads();

    const int tx = threadIdx.x, ty = threadIdx.y;
    const int gx = bx0 + tx, gy = by0 + ty;
    float acc;
    const bool interior = (gy >= 2) && (gy <= A_ANG - 3) && (gx >= 2) && (gx <= DDET - 3);
    if (interior) {
        acc = sbias;
        #pragma unroll
        for (int a = 0; a < 9; a++)
            #pragma unroll
            for (int b = 0; b < 9; b++)
                acc = fmaf(t[ty + a][tx + b], sW[a * 9 + b], acc);
    } else {
        acc = b2[0];
        for (int dy = 0; dy < 5; dy++) {
            int hy = gy + dy - 2; if ((unsigned)hy >= A_ANG) continue;
            for (int dx = 0; dx < 5; dx++) {
                int hx = gx + dx - 2; if ((unsigned)hx >= DDET) continue;
                float a2 = sB[dy * 5 + dx];
                #pragma unroll
                for (int ey = 0; ey < 5; ey++)
                    #pragma unroll
                    for (int ex = 0; ex < 5; ex++)
                        a2 = fmaf(t[ty + dy + ey][tx + dx + ex],
                                  sG[(dy * 5 + dx) * 25 + ey * 5 + ex], a2);
                acc += a2;
            }
        }
    }
    const int idx = gy * DDET + gx;
    sino_pred[idx] = acc;
    g_pad[gy * PADW + POFF + gx] = make_float2(t[ty + 4][tx + 4], acc);
}

// ---------------------------------------------------------------------------
// Kernel 2: dual fan-beam backprojection.
// 32x32 tile / 1024 threads (144 blocks ~ 1/SM). __launch_bounds__(1024, 1)
// grants the 64-reg budget so the 4-angle batch compiles with 8 LDG.64 truly
// outstanding (prior rounds: ptxas capped regs at 31 for the 2-block ladder
// and serialized the batch). Floor via 2^23 trick; x576 folded into X5/Y5.
// ---------------------------------------------------------------------------
__global__ void __launch_bounds__(1024, 1) backproj_kernel(
    const float* __restrict__ angles,
    float* __restrict__ img_sino)
{
    __shared__ float2 s_ang[A_ANG];
    const int tid = threadIdx.x;
    if (tid < A_ANG) {
        float sv, cv;
        sincosf(angles[tid], &sv, &cv);
        s_ang[tid] = make_float2(cv, sv);
    }
    __syncthreads();

    // warp footprint 8x4; warps tiled 4 across x, 8 down y
    const int lane = tid & 31, wid = tid >> 5;
    const int lx = lane & 7,  ly = lane >> 3;      // 8 x 4
    const int wx = wid & 3,   wy = wid >> 2;       // 4 x 8
    const int x = blockIdx.x * 32 + wx * 8 + lx;
    const int y = blockIdx.y * 32 + wy * 4 + ly;
    const float X  = (float)x - 191.5f;
    const float Y  = (float)y - 191.5f;
    const float X5 = X * 576.0f;
    const float Y5 = Y * 576.0f;

    float accA = 0.f, accB = 0.f;
    for (int a = 0; a < A_ANG; a += 4) {
        float2 v0[4], v1[4];
        float fr[4];
        #pragma unroll
        for (int j = 0; j < 4; j++) {
            const float2 cs = s_ang[a + j];
            const float px5 = fmaf(cs.x, X5, cs.y * Y5);       // 576 * px
            const float py  = fmaf(-cs.y, X, cs.x * Y);
            const float f   = __fdividef(1.0f, 576.0f + py);
            const float sb  = fmaf(px5, f, 287.0f);            // s - 0.5
            const float u   = sb + CMAGIC;                     // RN round
            const int   i0  = __float_as_int(u) - CBITS;
            const float r   = u - CMAGIC;
            fr[j] = (sb - r) + 0.5f;                           // in [0, 1]
            const float2* __restrict__ row = &g_pad[(a + j) * PADW + POFF];
            v0[j] = __ldg(&row[i0]);
            v1[j] = __ldg(&row[i0 + 1]);
        }
        #pragma unroll
        for (int j = 0; j < 4; j++) {
            const float w0 = 1.0f - fr[j];
            accA = fmaf(v0[j].x, w0, accA);
            accA = fmaf(v1[j].x, fr[j], accA);
            accB = fmaf(v0[j].y, w0, accB);
            accB = fmaf(v1[j].y, fr[j], accB);
        }
    }
    const int p = y * W_IMG + x;
    g_img[p]    = accA;
    img_sino[p] = accB;
}

// ---------------------------------------------------------------------------
// Kernel 3: conv3 (2->1, 3x3, pad1), smem-tiled, 32x16 blocks.
// ---------------------------------------------------------------------------
#define DTX 32
#define DTY 16
__global__ void __launch_bounds__(DTX * DTY) conv3_kernel(
    const float* __restrict__ w3, const float* __restrict__ b3,
    const float* __restrict__ img_sino,
    float* __restrict__ img_pred)
{
    __shared__ float sI[DTY + 2][DTX + 2];
    __shared__ float sS[DTY + 2][DTX + 2];
    __shared__ float s_w[18];
    __shared__ float s_b;

    const int tid = threadIdx.y * DTX + threadIdx.x;
    if (tid < 18) s_w[tid] = w3[tid];
    if (tid == 18) s_b = b3[0];

    const int bx0 = blockIdx.x * DTX, by0 = blockIdx.y * DTY;
    for (int i = tid; i < (DTY + 2) * (DTX + 2); i += DTX * DTY) {
        int ly = i / (DTX + 2), lx = i % (DTX + 2);
        int gy = by0 - 1 + ly, gx = bx0 - 1 + lx;
        float vi = 0.0f, vs = 0.0f;
        if ((unsigned)gy < W_IMG && (unsigned)gx < W_IMG) {
            int q = gy * W_IMG + gx;
            vi = g_img[q];
            vs = __ldg(&img_sino[q]);
        }
        sI[ly][lx] = vi;
        sS[ly][lx] = vs;
    }
    __syncthreads();

    const int tx = threadIdx.x, ty = threadIdx.y;
    float acc = s_b;
    #pragma unroll
    for (int ky = 0; ky < 3; ky++)
        #pragma unroll
        for (int kx = 0; kx < 3; kx++) {
            acc = fmaf(sI[ty + ky][tx + kx], s_w[ky * 3 + kx],     acc);
            acc = fmaf(sS[ty + ky][tx + kx], s_w[9 + ky * 3 + kx], acc);
        }
    img_pred[(by0 + ty) * W_IMG + bx0 + tx] = acc;
}

// ---------------------------------------------------------------------------
extern "C" void kernel_launch(void* const* d_in, const int* in_sizes, int n_in,
                              void* d_out, int out_size)
{
    const float* sino   = (const float*)d_in[0];
    const float* angles = (const float*)d_in[1];
    const float* w1     = (const float*)d_in[2];
    const float* b1     = (const float*)d_in[3];
    const float* w2     = (const float*)d_in[4];
    const float* b2     = (const float*)d_in[5];
    const float* w3     = (const float*)d_in[6];
    const float* b3     = (const float*)d_in[7];

    float* out       = (float*)d_out;
    float* sino_pred = out;                               // 192*576 = 110592
    float* img_sino  = out + A_ANG * DDET;                // 384*384 = 147456
    float* img_pred  = out + A_ANG * DDET + WW;

    precompute_kernel<<<1, 640>>>(w1, b1, w2, b2);

    dim3 grid1(DDET / CTX, A_ANG / CTY);
    dim3 block1(CTX, CTY);
    conv12_kernel<<<grid1, block1>>>(sino, b2, sino_pred);

    dim3 grid2(W_IMG / 32, W_IMG / 32);
    backproj_kernel<<<grid2, 1024>>>(angles, img_sino);

    dim3 grid3(W_IMG / DTX, W_IMG / DTY);
    dim3 block3(DTX, DTY);
    conv3_kernel<<<grid3, block3>>>(w3, b3, img_sino, img_pred);
}

// round 15
// speedup vs baseline: 1.0842x; 1.0842x over previous
#include <cuda_runtime.h>

#define A_ANG 192
#define DDET  576
#define W_IMG 384
#define WW    (W_IMG * W_IMG)
#define PADW  672
#define POFF  24

// Scratch (__device__ globals: allocation-free). g_pad is zero-initialized at
// module load; padding slots are never written, so they stay zero across all
// graph replays (out-of-range detector taps contribute exactly 0).
__device__ float2 g_pad[A_ANG * PADW];     // 1.0 MB packed (sino, pred) table
__device__ float  g_img[WW];               // backprojection of raw sino
__device__ float  g_G[625];                // G[d][e] = sum_c w2[c,d]*w1[c,e]
__device__ float  g_B[25];                 // B[d]    = sum_c w2[c,d]*b1[c]
__device__ float  g_W[81];                 // interior 9x9 composite kernel
__device__ float  g_bias[1];               // b2 + sum_d B[d]

// ---------------------------------------------------------------------------
// Kernel 0: build composite-conv tables (1 block, trivial cost)
// ---------------------------------------------------------------------------
__global__ void __launch_bounds__(640) precompute_kernel(
    const float* __restrict__ w1, const float* __restrict__ b1,
    const float* __restrict__ w2, const float* __restrict__ b2)
{
    __shared__ float sG[625];
    const int tid = threadIdx.x;
    if (tid < 625) {
        int d = tid / 25, e = tid % 25;
        float g = 0.0f;
        #pragma unroll
        for (int c = 0; c < 16; c++) g = fmaf(w2[c * 25 + d], w1[c * 25 + e], g);
        sG[tid] = g;
        g_G[tid] = g;
    }
    if (tid < 25) {
        float s = 0.0f;
        #pragma unroll
        for (int c = 0; c < 16; c++) s = fmaf(w2[c * 25 + tid], b1[c], s);
        g_B[tid] = s;
    }
    __syncthreads();
    if (tid < 81) {
        int tty = tid / 9, ttx = tid % 9;
        float w = 0.0f;
        for (int dy = 0; dy < 5; dy++) {
            int ey = tty - dy; if (ey < 0 || ey > 4) continue;
            for (int dx = 0; dx < 5; dx++) {
                int ex = ttx - dx; if (ex < 0 || ex > 4) continue;
                w += sG[(dy * 5 + dx) * 25 + ey * 5 + ex];
            }
        }
        g_W[tid] = w;
    }
    if (tid == 0) {
        float bias = b2[0];
        #pragma unroll
        for (int c = 0; c < 16; c++) {
            float s2 = 0.0f;
            #pragma unroll
            for (int d = 0; d < 25; d++) s2 += w2[c * 25 + d];
            bias = fmaf(s2, b1[c], bias);
        }
        g_bias[0] = bias;
    }
}

// ---------------------------------------------------------------------------
// Kernel 1: composite conv (sino -> sino_pred), writes packed padded sinogram.
// Interior pixels: 9x9 kernel W (81 FMA). Border pixels: exact per-d formula.
// Only blocks touching the image border load the big sG/sB tables.
// ---------------------------------------------------------------------------
#define CTX 32
#define CTY 8
__global__ void __launch_bounds__(CTX * CTY) conv12_kernel(
    const float* __restrict__ sino,
    const float* __restrict__ b2,
    float* __restrict__ sino_pred)
{
    __shared__ float t[CTY + 8][CTX + 8];   // 16 x 40, halo 4, zero-padded
    __shared__ float sW[81];
    __shared__ float sG[625];
    __shared__ float sB[25];
    __shared__ float sbias;

    const int tid = threadIdx.y * CTX + threadIdx.x;
    const int bx0 = blockIdx.x * CTX, by0 = blockIdx.y * CTY;

    // block-uniform: does this block contain any border pixel?
    const bool has_border = (by0 == 0) || (by0 + CTY >= A_ANG) ||
                            (bx0 == 0) || (bx0 + CTX >= DDET);

    if (tid < 81) sW[tid] = g_W[tid];
    if (tid == 81) sbias = g_bias[0];
    if (has_border) {
        for (int i = tid; i < 625; i += CTX * CTY) sG[i] = g_G[i];
        if (tid < 25) sB[tid] = g_B[tid];
    }

    for (int i = tid; i < (CTY + 8) * (CTX + 8); i += CTX * CTY) {
        int ly = i / (CTX + 8), lx = i % (CTX + 8);
        int gy = by0 - 4 + ly, gx = bx0 - 4 + lx;
        float v = 0.0f;
        if ((unsigned)gy < A_ANG && (unsigned)gx < DDET) v = sino[gy * DDET + gx];
        t[ly][lx] = v;
    }
    __syncthreads();

    const int tx = threadIdx.x, ty = threadIdx.y;
    const int gx = bx0 + tx, gy = by0 + ty;
    float acc;
    const bool interior = (gy >= 2) && (gy <= A_ANG - 3) && (gx >= 2) && (gx <= DDET - 3);
    if (interior) {
        acc = sbias;
        #pragma unroll
        for (int a = 0; a < 9; a++)
            #pragma unroll
            for (int b = 0; b < 9; b++)
                acc = fmaf(t[ty + a][tx + b], sW[a * 9 + b], acc);
    } else {
        acc = b2[0];
        for (int dy = 0; dy < 5; dy++) {
            int hy = gy + dy - 2; if ((unsigned)hy >= A_ANG) continue;
            for (int dx = 0; dx < 5; dx++) {
                int hx = gx + dx - 2; if ((unsigned)hx >= DDET) continue;
                float a2 = sB[dy * 5 + dx];
                #pragma unroll
                for (int ey = 0; ey < 5; ey++)
                    #pragma unroll
                    for (int ex = 0; ex < 5; ex++)
                        a2 = fmaf(t[ty + dy + ey][tx + dx + ex],
                                  sG[(dy * 5 + dx) * 25 + ey * 5 + ex], a2);
                acc += a2;
            }
        }
    }
    const int idx = gy * DDET + gx;
    sino_pred[idx] = acc;
    g_pad[gy * PADW + POFF + gx] = make_float2(t[ty + 4][tx + 4], acc);
}

// ---------------------------------------------------------------------------
// Kernel 2: dual fan-beam backprojection (R9-proven config).
// 32x32 pixel tile / 1024 threads (144 blocks ~ 1/SM). 2-angle unroll.
// Row pointer stepped by PADW per angle (no per-angle index multiply).
// ---------------------------------------------------------------------------
__global__ void __launch_bounds__(1024) backproj_kernel(
    const float* __restrict__ angles,
    float* __restrict__ img_sino)
{
    __shared__ float2 s_ang[A_ANG];
    const int tid = threadIdx.x;
    if (tid < A_ANG) {
        float sv, cv;
        sincosf(angles[tid], &sv, &cv);
        s_ang[tid] = make_float2(cv, sv);
    }
    __syncthreads();

    // warp footprint 8x4; warps tiled 4 across x, 8 down y
    const int lane = tid & 31, wid = tid >> 5;
    const int lx = lane & 7,  ly = lane >> 3;      // 8 x 4
    const int wx = wid & 3,   wy = wid >> 2;       // 4 x 8
    const int x = blockIdx.x * 32 + wx * 8 + lx;
    const int y = blockIdx.y * 32 + wy * 4 + ly;
    const float X = (float)x - 191.5f;
    const float Y = (float)y - 191.5f;

    const float2* __restrict__ row = &g_pad[POFF];
    float accA = 0.f, accB = 0.f;
    for (int a = 0; a < A_ANG; a += 2) {
        float2 v0[2], v1[2];
        float fr[2];
        #pragma unroll
        for (int j = 0; j < 2; j++) {
            const float2 cs = s_ang[a + j];
            const float px = fmaf(cs.x, X, cs.y * Y);
            const float py = fmaf(-cs.y, X, cs.x * Y);
            const float f  = __fdividef(576.0f, 576.0f + py);
            const float s  = fmaf(px, f, 287.5f);
            const int i0   = __float2int_rd(s);
            fr[j] = s - (float)i0;
            v0[j] = __ldg(&row[j * PADW + i0]);
            v1[j] = __ldg(&row[j * PADW + i0 + 1]);
        }
        row += 2 * PADW;
        #pragma unroll
        for (int j = 0; j < 2; j++) {
            const float w0 = 1.0f - fr[j];
            accA = fmaf(v0[j].x, w0, accA);
            accA = fmaf(v1[j].x, fr[j], accA);
            accB = fmaf(v0[j].y, w0, accB);
            accB = fmaf(v1[j].y, fr[j], accB);
        }
    }
    const int p = y * W_IMG + x;
    g_img[p]    = accA;
    img_sino[p] = accB;
}

// ---------------------------------------------------------------------------
// Kernel 3: conv3 (2->1, 3x3, pad1), smem-tiled, 32x16 blocks.
// ---------------------------------------------------------------------------
#define DTX 32
#define DTY 16
__global__ void __launch_bounds__(DTX * DTY) conv3_kernel(
    const float* __restrict__ w3, const float* __restrict__ b3,
    const float* __restrict__ img_sino,
    float* __restrict__ img_pred)
{
    __shared__ float sI[DTY + 2][DTX + 2];
    __shared__ float sS[DTY + 2][DTX + 2];
    __shared__ float s_w[18];
    __shared__ float s_b;

    const int tid = threadIdx.y * DTX + threadIdx.x;
    if (tid < 18) s_w[tid] = w3[tid];
    if (tid == 18) s_b = b3[0];

    const int bx0 = blockIdx.x * DTX, by0 = blockIdx.y * DTY;
    for (int i = tid; i < (DTY + 2) * (DTX + 2); i += DTX * DTY) {
        int ly = i / (DTX + 2), lx = i % (DTX + 2);
        int gy = by0 - 1 + ly, gx = bx0 - 1 + lx;
        float vi = 0.0f, vs = 0.0f;
        if ((unsigned)gy < W_IMG && (unsigned)gx < W_IMG) {
            int q = gy * W_IMG + gx;
            vi = g_img[q];
            vs = __ldg(&img_sino[q]);
        }
        sI[ly][lx] = vi;
        sS[ly][lx] = vs;
    }
    __syncthreads();

    const int tx = threadIdx.x, ty = threadIdx.y;
    float acc = s_b;
    #pragma unroll
    for (int ky = 0; ky < 3; ky++)
        #pragma unroll
        for (int kx = 0; kx < 3; kx++) {
            acc = fmaf(sI[ty + ky][tx + kx], s_w[ky * 3 + kx],     acc);
            acc = fmaf(sS[ty + ky][tx + kx], s_w[9 + ky * 3 + kx], acc);
        }
    img_pred[(by0 + ty) * W_IMG + bx0 + tx] = acc;
}

// ---------------------------------------------------------------------------
extern "C" void kernel_launch(void* const* d_in, const int* in_sizes, int n_in,
                              void* d_out, int out_size)
{
    const float* sino   = (const float*)d_in[0];
    const float* angles = (const float*)d_in[1];
    const float* w1     = (const float*)d_in[2];
    const float* b1     = (const float*)d_in[3];
    const float* w2     = (const float*)d_in[4];
    const float* b2     = (const float*)d_in[5];
    const float* w3     = (const float*)d_in[6];
    const float* b3     = (const float*)d_in[7];

    float* out       = (float*)d_out;
    float* sino_pred = out;                               // 192*576 = 110592
    float* img_sino  = out + A_ANG * DDET;                // 384*384 = 147456
    float* img_pred  = out + A_ANG * DDET + WW;

    precompute_kernel<<<1, 640>>>(w1, b1, w2, b2);

    dim3 grid1(DDET / CTX, A_ANG / CTY);
    dim3 block1(CTX, CTY);
    conv12_kernel<<<grid1, block1>>>(sino, b2, sino_pred);

    dim3 grid2(W_IMG / 32, W_IMG / 32);
    backproj_kernel<<<grid2, 1024>>>(angles, img_sino);

    dim3 grid3(W_IMG / DTX, W_IMG / DTY);
    dim3 block3(DTX, DTY);
    conv3_kernel<<<grid3, block3>>>(w3, b3, img_sino, img_pred);
}

// round 16
// speedup vs baseline: 1.1723x; 1.0813x over previous
#include <cuda_runtime.h>

#define A_ANG 192
#define DDET  576
#define W_IMG 384
#define WW    (W_IMG * W_IMG)
#define PADW  672
#define POFF  24

// Scratch (__device__ globals: allocation-free). g_pad is zero-initialized at
// module load; padding slots are never written, so they stay zero across all
// graph replays (out-of-range detector taps contribute exactly 0).
__device__ float2 g_pad[A_ANG * PADW];     // 1.0 MB packed (sino, pred) table
__device__ float  g_img[WW];               // backprojection of raw sino

// ---------------------------------------------------------------------------
// Kernel 1: composite conv (sino -> sino_pred), writes packed padded sinogram.
// Tables are built IN-BLOCK from smem-staged weights (816 coalesced LDGs;
// the R4/R11 regressions came from per-entry scattered LDGs, not the FMAs):
//   sG[d][e] = sum_c w2[c,d]*w1[c,e]      (~2.5 entries/thread, smem reads)
//   sW9[a][b] = sum_{d+e=(a,b)} sG        (81 threads)
//   sB[d] = sum_c w2[c,d]*b1[c]; bias = b2 + sum_d sB[d]
// Interior pixels: 9x9 kernel (81 FMA). Border pixels: exact per-d formula.
// ---------------------------------------------------------------------------
#define CTX 32
#define CTY 8
__global__ void __launch_bounds__(CTX * CTY) conv12_kernel(
    const float* __restrict__ sino,
    const float* __restrict__ w1, const float* __restrict__ b1,
    const float* __restrict__ w2, const float* __restrict__ b2,
    float* __restrict__ sino_pred)
{
    __shared__ float t[CTY + 8][CTX + 8];   // 16 x 40, halo 4, zero-padded
    __shared__ float sw1[400], sw2[400], sb1[16];
    __shared__ float sG[625];
    __shared__ float sB[25];
    __shared__ float sW[81];
    __shared__ float sbias;

    const int tid = threadIdx.y * CTX + threadIdx.x;
    const int bx0 = blockIdx.x * CTX, by0 = blockIdx.y * CTY;

    // coalesced weight staging (in flight together with the tile loads)
    for (int i = tid; i < 400; i += CTX * CTY) { sw1[i] = w1[i]; sw2[i] = w2[i]; }
    if (tid < 16) sb1[tid] = b1[tid];

    for (int i = tid; i < (CTY + 8) * (CTX + 8); i += CTX * CTY) {
        int ly = i / (CTX + 8), lx = i % (CTX + 8);
        int gy = by0 - 4 + ly, gx = bx0 - 4 + lx;
        float v = 0.0f;
        if ((unsigned)gy < A_ANG && (unsigned)gx < DDET) v = sino[gy * DDET + gx];
        t[ly][lx] = v;
    }
    __syncthreads();

    // G and B from smem-staged weights
    for (int i = tid; i < 625; i += CTX * CTY) {
        int d = i / 25, e = i % 25;
        float g = 0.0f;
        #pragma unroll
        for (int c = 0; c < 16; c++) g = fmaf(sw2[c * 25 + d], sw1[c * 25 + e], g);
        sG[i] = g;
    }
    if (tid < 25) {
        float s = 0.0f;
        #pragma unroll
        for (int c = 0; c < 16; c++) s = fmaf(sw2[c * 25 + tid], sb1[c], s);
        sB[tid] = s;
    }
    __syncthreads();
    if (tid < 81) {
        int tty = tid / 9, ttx = tid % 9;
        float w = 0.0f;
        for (int dy = 0; dy < 5; dy++) {
            int ey = tty - dy; if (ey < 0 || ey > 4) continue;
            for (int dx = 0; dx < 5; dx++) {
                int ex = ttx - dx; if (ex < 0 || ex > 4) continue;
                w += sG[(dy * 5 + dx) * 25 + ey * 5 + ex];
            }
        }
        sW[tid] = w;
    }
    if (tid == 96) {
        float bias = b2[0];
        #pragma unroll
        for (int d = 0; d < 25; d++) bias += sB[d];
        sbias = bias;
    }
    __syncthreads();

    const int tx = threadIdx.x, ty = threadIdx.y;
    const int gx = bx0 + tx, gy = by0 + ty;
    float acc;
    const bool interior = (gy >= 2) && (gy <= A_ANG - 3) && (gx >= 2) && (gx <= DDET - 3);
    if (interior) {
        acc = sbias;
        #pragma unroll
        for (int a = 0; a < 9; a++)
            #pragma unroll
            for (int b = 0; b < 9; b++)
                acc = fmaf(t[ty + a][tx + b], sW[a * 9 + b], acc);
    } else {
        acc = b2[0];
        for (int dy = 0; dy < 5; dy++) {
            int hy = gy + dy - 2; if ((unsigned)hy >= A_ANG) continue;
            for (int dx = 0; dx < 5; dx++) {
                int hx = gx + dx - 2; if ((unsigned)hx >= DDET) continue;
                float a2 = sB[dy * 5 + dx];
                #pragma unroll
                for (int ey = 0; ey < 5; ey++)
                    #pragma unroll
                    for (int ex = 0; ex < 5; ex++)
                        a2 = fmaf(t[ty + dy + ey][tx + dx + ex],
                                  sG[(dy * 5 + dx) * 25 + ey * 5 + ex], a2);
                acc += a2;
            }
        }
    }
    const int idx = gy * DDET + gx;
    sino_pred[idx] = acc;
    g_pad[gy * PADW + POFF + gx] = make_float2(t[ty + 4][tx + 4], acc);
}

// ---------------------------------------------------------------------------
// Kernel 2: dual fan-beam backprojection (R9/R15-proven config).
// 32x32 pixel tile / 1024 threads (144 blocks ~ 1/SM). 2-angle unroll.
// Row pointer stepped by PADW per angle (no per-angle index multiply).
// ---------------------------------------------------------------------------
__global__ void __launch_bounds__(1024) backproj_kernel(
    const float* __restrict__ angles,
    float* __restrict__ img_sino)
{
    __shared__ float2 s_ang[A_ANG];
    const int tid = threadIdx.x;
    if (tid < A_ANG) {
        float sv, cv;
        sincosf(angles[tid], &sv, &cv);
        s_ang[tid] = make_float2(cv, sv);
    }
    __syncthreads();

    // warp footprint 8x4; warps tiled 4 across x, 8 down y
    const int lane = tid & 31, wid = tid >> 5;
    const int lx = lane & 7,  ly = lane >> 3;      // 8 x 4
    const int wx = wid & 3,   wy = wid >> 2;       // 4 x 8
    const int x = blockIdx.x * 32 + wx * 8 + lx;
    const int y = blockIdx.y * 32 + wy * 4 + ly;
    const float X = (float)x - 191.5f;
    const float Y = (float)y - 191.5f;

    const float2* __restrict__ row = &g_pad[POFF];
    float accA = 0.f, accB = 0.f;
    for (int a = 0; a < A_ANG; a += 2) {
        float2 v0[2], v1[2];
        float fr[2];
        #pragma unroll
        for (int j = 0; j < 2; j++) {
            const float2 cs = s_ang[a + j];
            const float px = fmaf(cs.x, X, cs.y * Y);
            const float py = fmaf(-cs.y, X, cs.x * Y);
            const float f  = __fdividef(576.0f, 576.0f + py);
            const float s  = fmaf(px, f, 287.5f);
            const int i0   = __float2int_rd(s);
            fr[j] = s - (float)i0;
            v0[j] = __ldg(&row[j * PADW + i0]);
            v1[j] = __ldg(&row[j * PADW + i0 + 1]);
        }
        row += 2 * PADW;
        #pragma unroll
        for (int j = 0; j < 2; j++) {
            const float w0 = 1.0f - fr[j];
            accA = fmaf(v0[j].x, w0, accA);
            accA = fmaf(v1[j].x, fr[j], accA);
            accB = fmaf(v0[j].y, w0, accB);
            accB = fmaf(v1[j].y, fr[j], accB);
        }
    }
    const int p = y * W_IMG + x;
    g_img[p]    = accA;
    img_sino[p] = accB;
}

// ---------------------------------------------------------------------------
// Kernel 3: conv3 (2->1, 3x3, pad1), smem-tiled, 32x16 blocks.
// ---------------------------------------------------------------------------
#define DTX 32
#define DTY 16
__global__ void __launch_bounds__(DTX * DTY) conv3_kernel(
    const float* __restrict__ w3, const float* __restrict__ b3,
    const float* __restrict__ img_sino,
    float* __restrict__ img_pred)
{
    __shared__ float sI[DTY + 2][DTX + 2];
    __shared__ float sS[DTY + 2][DTX + 2];
    __shared__ float s_w[18];
    __shared__ float s_b;

    const int tid = threadIdx.y * DTX + threadIdx.x;
    if (tid < 18) s_w[tid] = w3[tid];
    if (tid == 18) s_b = b3[0];

    const int bx0 = blockIdx.x * DTX, by0 = blockIdx.y * DTY;
    for (int i = tid; i < (DTY + 2) * (DTX + 2); i += DTX * DTY) {
        int ly = i / (DTX + 2), lx = i % (DTX + 2);
        int gy = by0 - 1 + ly, gx = bx0 - 1 + lx;
        float vi = 0.0f, vs = 0.0f;
        if ((unsigned)gy < W_IMG && (unsigned)gx < W_IMG) {
            int q = gy * W_IMG + gx;
            vi = g_img[q];
            vs = __ldg(&img_sino[q]);
        }
        sI[ly][lx] = vi;
        sS[ly][lx] = vs;
    }
    __syncthreads();

    const int tx = threadIdx.x, ty = threadIdx.y;
    float acc = s_b;
    #pragma unroll
    for (int ky = 0; ky < 3; ky++)
        #pragma unroll
        for (int kx = 0; kx < 3; kx++) {
            acc = fmaf(sI[ty + ky][tx + kx], s_w[ky * 3 + kx],     acc);
            acc = fmaf(sS[ty + ky][tx + kx], s_w[9 + ky * 3 + kx], acc);
        }
    img_pred[(by0 + ty) * W_IMG + bx0 + tx] = acc;
}

// ---------------------------------------------------------------------------
extern "C" void kernel_launch(void* const* d_in, const int* in_sizes, int n_in,
                              void* d_out, int out_size)
{
    const float* sino   = (const float*)d_in[0];
    const float* angles = (const float*)d_in[1];
    const float* w1     = (const float*)d_in[2];
    const float* b1     = (const float*)d_in[3];
    const float* w2     = (const float*)d_in[4];
    const float* b2     = (const float*)d_in[5];
    const float* w3     = (const float*)d_in[6];
    const float* b3     = (const float*)d_in[7];

    float* out       = (float*)d_out;
    float* sino_pred = out;                               // 192*576 = 110592
    float* img_sino  = out + A_ANG * DDET;                // 384*384 = 147456
    float* img_pred  = out + A_ANG * DDET + WW;

    dim3 grid1(DDET / CTX, A_ANG / CTY);
    dim3 block1(CTX, CTY);
    conv12_kernel<<<grid1, block1>>>(sino, w1, b1, w2, b2, sino_pred);

    dim3 grid2(W_IMG / 32, W_IMG / 32);
    backproj_kernel<<<grid2, 1024>>>(angles, img_sino);

    dim3 grid3(W_IMG / DTX, W_IMG / DTY);
    dim3 block3(DTX, DTY);
    conv3_kernel<<<grid3, block3>>>(w3, b3, img_sino, img_pred);
}